// round 1
// baseline (speedup 1.0000x reference)
#include <cuda_runtime.h>
#include <mma.h>

using namespace nvcuda;

// Shapes (fixed for this problem)
#define NB   256      // batch
#define CIN  2048
#define LL   150
#define CC   256      // channels after value conv
#define H1   8192
#define NOUT 2048

// Scratch (allocation-free rule: __device__ globals)
__device__ float g_pv [NB * CC * LL];   // value projection
__device__ float g_q  [NB * CC * LL];
__device__ float g_k  [NB * CC * LL];
__device__ float g_att[NB * LL * LL];   // energy -> softmax in place
__device__ float g_o2 [NB * CC * LL];   // gamma*attn_out + pv  (flat fc1 input)
__device__ float g_h  [NB * H1];        // fc1 output

// ---------------------------------------------------------------------------
// Generic tf32 WMMA GEMM:
//   C[z, m, n] = sum_k A[z](m,k) * B[z](k,n)  (+ bias)  (+ gamma residual)
// A_KC:  A element at  A + z*sAz + m*ldA + k   (k contiguous)   else k*ldA + m
// B_KC:  B element at  B + z*sBz + n*ldB + k   (k contiguous)   else k*ldB + n
// BIAS_MODE: 0 none, 1 bias[n], 2 bias[m]
// GAMMA: C = gamma[0]*acc + resid[z*sRz + m*ldC + n]
// Block tile 128x64, BK=16, 256 threads (8 warps of 32x32), m16n16k8 tf32.
// ---------------------------------------------------------------------------
template<bool A_KC, bool B_KC, int BIAS_MODE, bool GAMMA>
__global__ __launch_bounds__(256)
void gemm_tf32(const float* __restrict__ A, long ldA, long sAz,
               const float* __restrict__ Bm, long ldB, long sBz,
               float* __restrict__ Cm, long ldC, long sCz,
               const float* __restrict__ bias,
               const float* __restrict__ resid, long sRz,
               const float* __restrict__ gamma,
               int M, int N, int K)
{
    constexpr int BM = 128, BN = 64, BK = 16;
    __shared__ float As[BM * 20];   // lda = 20 (mult of 4)
    __shared__ float Bs[BK * 68];   // ldb = 68 (mult of 4)
    __shared__ float Cst[8 * 256];  // per-warp epilogue staging

    const int tid  = threadIdx.x;
    const int wid  = tid >> 5;
    const int lane = tid & 31;
    const int z    = blockIdx.z;
    const int m0   = blockIdx.y * BM;
    const int n0   = blockIdx.x * BN;
    const int warpM = wid >> 1;   // 0..3
    const int warpN = wid & 1;    // 0..1

    const float* Az = A  + (long)z * sAz;
    const float* Bz = Bm + (long)z * sBz;
    float*       Cz = Cm + (long)z * sCz;

    wmma::fragment<wmma::accumulator, 16, 16, 8, float> acc[2][2];
    #pragma unroll
    for (int i = 0; i < 2; i++)
        #pragma unroll
        for (int j = 0; j < 2; j++)
            wmma::fill_fragment(acc[i][j], 0.0f);

    for (int k0 = 0; k0 < K; k0 += BK) {
        // ---- load A tile -> As[m][k] ----
        if (A_KC) {
            #pragma unroll
            for (int i = tid; i < BM * BK; i += 256) {
                int m = i >> 4, k = i & 15;
                int gm = m0 + m, gk = k0 + k;
                float v = 0.0f;
                if (gm < M && gk < K) v = Az[(long)gm * ldA + gk];
                As[m * 20 + k] = v;
            }
        } else {
            #pragma unroll
            for (int i = tid; i < BM * BK; i += 256) {
                int m = i & 127, k = i >> 7;
                int gm = m0 + m, gk = k0 + k;
                float v = 0.0f;
                if (gm < M && gk < K) v = Az[(long)gk * ldA + gm];
                As[m * 20 + k] = v;
            }
        }
        // ---- load B tile -> Bs[k][n] ----
        if (B_KC) {
            #pragma unroll
            for (int i = tid; i < BK * BN; i += 256) {
                int k = i & 15, n = i >> 4;
                int gn = n0 + n, gk = k0 + k;
                float v = 0.0f;
                if (gn < N && gk < K) v = Bz[(long)gn * ldB + gk];
                Bs[k * 68 + n] = v;
            }
        } else {
            #pragma unroll
            for (int i = tid; i < BK * BN; i += 256) {
                int n = i & 63, k = i >> 6;
                int gn = n0 + n, gk = k0 + k;
                float v = 0.0f;
                if (gn < N && gk < K) v = Bz[(long)gk * ldB + gn];
                Bs[k * 68 + n] = v;
            }
        }
        __syncthreads();

        #pragma unroll
        for (int kk = 0; kk < BK; kk += 8) {
            wmma::fragment<wmma::matrix_a, 16, 16, 8, wmma::precision::tf32, wmma::row_major> af[2];
            wmma::fragment<wmma::matrix_b, 16, 16, 8, wmma::precision::tf32, wmma::row_major> bf[2];
            wmma::load_matrix_sync(af[0], &As[(warpM * 32 +  0) * 20 + kk], 20);
            wmma::load_matrix_sync(af[1], &As[(warpM * 32 + 16) * 20 + kk], 20);
            wmma::load_matrix_sync(bf[0], &Bs[kk * 68 + warpN * 32 +  0], 68);
            wmma::load_matrix_sync(bf[1], &Bs[kk * 68 + warpN * 32 + 16], 68);
            #pragma unroll
            for (int t = 0; t < af[0].num_elements; t++) {
                af[0].x[t] = wmma::__float_to_tf32(af[0].x[t]);
                af[1].x[t] = wmma::__float_to_tf32(af[1].x[t]);
            }
            #pragma unroll
            for (int t = 0; t < bf[0].num_elements; t++) {
                bf[0].x[t] = wmma::__float_to_tf32(bf[0].x[t]);
                bf[1].x[t] = wmma::__float_to_tf32(bf[1].x[t]);
            }
            #pragma unroll
            for (int i = 0; i < 2; i++)
                #pragma unroll
                for (int j = 0; j < 2; j++)
                    wmma::mma_sync(acc[i][j], af[i], bf[j], acc[i][j]);
        }
        __syncthreads();
    }

    // ---- epilogue: stage frags through shared, bounds-checked write ----
    float* ws = &Cst[wid * 256];
    const float gval = GAMMA ? gamma[0] : 0.0f;
    #pragma unroll
    for (int i = 0; i < 2; i++) {
        #pragma unroll
        for (int j = 0; j < 2; j++) {
            wmma::store_matrix_sync(ws, acc[i][j], 16, wmma::mem_row_major);
            __syncwarp();
            int gm0 = m0 + warpM * 32 + i * 16;
            int gn0 = n0 + warpN * 32 + j * 16;
            for (int e = lane; e < 256; e += 32) {
                int r = e >> 4, c = e & 15;
                int gm = gm0 + r, gn = gn0 + c;
                if (gm < M && gn < N) {
                    float v = ws[e];
                    if (BIAS_MODE == 1) v += bias[gn];
                    else if (BIAS_MODE == 2) v += bias[gm];
                    if (GAMMA) v = gval * v + resid[(long)z * sRz + (long)gm * ldC + gn];
                    Cz[(long)gm * ldC + gn] = v;
                }
            }
            __syncwarp();
        }
    }
}

// ---------------------------------------------------------------------------
// Row softmax over length-150 rows; one warp per row.
// ---------------------------------------------------------------------------
__global__ __launch_bounds__(256)
void softmax150(float* __restrict__ att, int rows)
{
    int row  = blockIdx.x * 8 + (threadIdx.x >> 5);
    int lane = threadIdx.x & 31;
    if (row >= rows) return;
    float* p = att + (long)row * LL;

    float v[5];
    float mx = -1e30f;
    #pragma unroll
    for (int i = 0; i < 5; i++) {
        int j = lane + 32 * i;
        v[i] = (j < LL) ? p[j] : -1e30f;
        mx = fmaxf(mx, v[i]);
    }
    #pragma unroll
    for (int o = 16; o > 0; o >>= 1) mx = fmaxf(mx, __shfl_xor_sync(0xffffffffu, mx, o));

    float s = 0.0f;
    #pragma unroll
    for (int i = 0; i < 5; i++) { v[i] = expf(v[i] - mx); s += v[i]; }
    #pragma unroll
    for (int o = 16; o > 0; o >>= 1) s += __shfl_xor_sync(0xffffffffu, s, o);

    float inv = 1.0f / s;
    #pragma unroll
    for (int i = 0; i < 5; i++) {
        int j = lane + 32 * i;
        if (j < LL) p[j] = v[i] * inv;
    }
}

// ---------------------------------------------------------------------------
extern "C" void kernel_launch(void* const* d_in, const int* in_sizes, int n_in,
                              void* d_out, int out_size)
{
    (void)in_sizes; (void)n_in; (void)out_size;
    const float* x     = (const float*)d_in[0];
    const float* Wv    = (const float*)d_in[1];
    const float* bv    = (const float*)d_in[2];
    const float* Wq    = (const float*)d_in[3];
    const float* bq    = (const float*)d_in[4];
    const float* Wk    = (const float*)d_in[5];
    const float* bk    = (const float*)d_in[6];
    const float* gamma = (const float*)d_in[7];
    const float* W1    = (const float*)d_in[8];
    const float* b1    = (const float*)d_in[9];
    const float* W2    = (const float*)d_in[10];
    const float* b2    = (const float*)d_in[11];
    float* out = (float*)d_out;

    float *pv, *q, *k, *att, *o2, *h;
    cudaGetSymbolAddress((void**)&pv,  g_pv);
    cudaGetSymbolAddress((void**)&q,   g_q);
    cudaGetSymbolAddress((void**)&k,   g_k);
    cudaGetSymbolAddress((void**)&att, g_att);
    cudaGetSymbolAddress((void**)&o2,  g_o2);
    cudaGetSymbolAddress((void**)&h,   g_h);

    dim3 blk(256);
    const long CL = (long)CC * LL;       // 38400
    const long XL = (long)CIN * LL;      // 307200
    const long LLsq = (long)LL * LL;     // 22500

    // pv[b,o,l] = Wv[o,c] x[b,c,l] + bv[o]       M=256 N=150 K=2048
    gemm_tf32<true,  false, 2, false><<<dim3(3, 2, NB), blk>>>(
        Wv, CIN, 0,  x, LL, XL,  pv, LL, CL,  bv, nullptr, 0, nullptr,
        CC, LL, CIN);

    // q = Wq pv + bq ; k = Wk pv + bk            M=256 N=150 K=256
    gemm_tf32<true,  false, 2, false><<<dim3(3, 2, NB), blk>>>(
        Wq, CC, 0,  pv, LL, CL,  q, LL, CL,  bq, nullptr, 0, nullptr,
        CC, LL, CC);
    gemm_tf32<true,  false, 2, false><<<dim3(3, 2, NB), blk>>>(
        Wk, CC, 0,  pv, LL, CL,  k, LL, CL,  bk, nullptr, 0, nullptr,
        CC, LL, CC);

    // energy[b,i,j] = sum_c q[b,c,i] k[b,c,j]    M=150 N=150 K=256  (A m-contig)
    gemm_tf32<false, false, 0, false><<<dim3(3, 2, NB), blk>>>(
        q, LL, CL,  k, LL, CL,  att, LL, LLsq,  nullptr, nullptr, 0, nullptr,
        LL, LL, CC);

    // softmax over last axis, in place
    softmax150<<<(NB * LL + 7) / 8, blk>>>(att, NB * LL);

    // out2[b,c,l] = gamma * sum_m pv[b,c,m] att[b,l,m] + pv[b,c,l]
    //                                            M=256 N=150 K=150  (B k-contig)
    gemm_tf32<true,  true,  0, true ><<<dim3(3, 2, NB), blk>>>(
        pv, LL, CL,  att, LL, LLsq,  o2, LL, CL,  nullptr, pv, CL, gamma,
        CC, LL, LL);

    // fc1: h[b,j] = flat[b,:] . W1[j,:] + b1[j]  M=256 N=8192 K=38400
    gemm_tf32<true,  true,  1, false><<<dim3(H1 / 64, 2, 1), blk>>>(
        o2, CL, 0,  W1, CL, 0,  h, H1, 0,  b1, nullptr, 0, nullptr,
        NB, H1, (int)CL);

    // fc2: out[b,j] = h[b,:] . W2[j,:] + b2[j]   M=256 N=2048 K=8192
    gemm_tf32<true,  true,  1, false><<<dim3(NOUT / 64, 2, 1), blk>>>(
        h, H1, 0,  W2, H1, 0,  out, NOUT, 0,  b2, nullptr, 0, nullptr,
        NB, NOUT, H1);
}

// round 2
// speedup vs baseline: 1.2711x; 1.2711x over previous
#include <cuda_runtime.h>
#include <mma.h>
#include <cstdint>

using namespace nvcuda;

// Shapes (fixed for this problem)
#define NB   256      // batch
#define CIN  2048
#define LL   150
#define CC   256      // channels after value conv
#define H1   8192
#define NOUT 2048

// Scratch (allocation-free rule: __device__ globals)
__device__ float g_pv [NB * CC * LL];
__device__ float g_q  [NB * CC * LL];
__device__ float g_k  [NB * CC * LL];
__device__ float g_att[NB * LL * LL];
__device__ float g_o2 [NB * CC * LL];
__device__ float g_h  [NB * H1];

// ---------------------------------------------------------------------------
// cp.async helpers
// ---------------------------------------------------------------------------
__device__ __forceinline__ uint32_t sptr(const void* p) {
    return (uint32_t)__cvta_generic_to_shared(p);
}
__device__ __forceinline__ void cpa16(uint32_t d, const void* g, bool p) {
    asm volatile("cp.async.cg.shared.global [%0], [%1], 16, %2;\n"
                 :: "r"(d), "l"(g), "r"(p ? 16 : 0));
}
__device__ __forceinline__ void cpa8(uint32_t d, const void* g, bool p) {
    asm volatile("cp.async.ca.shared.global [%0], [%1], 8, %2;\n"
                 :: "r"(d), "l"(g), "r"(p ? 8 : 0));
}
__device__ __forceinline__ void cpa4(uint32_t d, const void* g, bool p) {
    asm volatile("cp.async.ca.shared.global [%0], [%1], 4, %2;\n"
                 :: "r"(d), "l"(g), "r"(p ? 4 : 0));
}
__device__ __forceinline__ void cp_commit() { asm volatile("cp.async.commit_group;\n"); }
template<int N> __device__ __forceinline__ void cp_wait() {
    asm volatile("cp.async.wait_group %0;\n" :: "n"(N));
}

// ---------------------------------------------------------------------------
// tf32 WMMA GEMM with cp.async double buffering.
//   C[z](m,n) = sum_k A[z](m,k) * B[z](k,n)  (+bias) (+gamma residual)
// A_KC: A element at m*ldA + k (k contiguous); else at k*ldA + m (m contig).
// B_KC: B element at n*ldB + k (k contiguous); else at k*ldB + n (n contig).
// AV/BV: cp.async byte width (16/8 for contiguous dims, 4 for A m-contig).
// BIAS: 0 none, 1 bias[n], 2 bias[m].   GAMMA: C = gamma[0]*acc + resid.
// 256 threads, 8 warps (BM/WM x BN/WN).
// ---------------------------------------------------------------------------
template<int BM, int BN, int BK, int WM, int WN,
         bool A_KC, int AV, bool B_KC, int BV, int BIAS, bool GAMMA>
__global__ __launch_bounds__(256, 1)
void gemm2(const float* __restrict__ A, long ldA, long sAz,
           const float* __restrict__ B, long ldB, long sBz,
           float* __restrict__ C, long ldC, long sCz,
           const float* __restrict__ bias,
           const float* __restrict__ resid, long sRz,
           const float* __restrict__ gamma,
           int M, int N, int K)
{
    constexpr int LDAS = BK + 4;
    constexpr int LDBS = B_KC ? (BK + 4) : (BN + 4);
    constexpr int ASZ  = BM * LDAS;
    constexpr int BSZ  = B_KC ? (BN * LDBS) : (BK * LDBS);
    constexpr int MW = BM / WM, NW = BN / WN;
    constexpr int MI = WM / 16, NI = WN / 16;
    static_assert(MW * NW == 8, "8 warps");

    extern __shared__ float sm[];
    float* As0 = sm;
    float* Bs0 = sm + 2 * ASZ;

    const int tid  = threadIdx.x;
    const int wid  = tid >> 5;
    const int lane = tid & 31;
    const int z    = blockIdx.z;
    const int m0   = blockIdx.y * BM;
    const int n0   = blockIdx.x * BN;
    const int warpM = wid % MW;
    const int warpN = wid / MW;

    const float* Az = A + (long)z * sAz;
    const float* Bz = B + (long)z * sBz;
    float*       Cz = C + (long)z * sCz;

    // ---- per-thread chunk precompute ----
    constexpr int AVF = A_KC ? (AV / 4) : 1;        // floats per chunk
    constexpr int ACH = BM * BK / AVF;
    constexpr int AIT = ACH / 256;
    static_assert(ACH % 256 == 0, "A chunks divisible");
    const float* aP[AIT]; int aRow[AIT], aKc[AIT]; bool aMok[AIT];
    #pragma unroll
    for (int i = 0; i < AIT; i++) {
        int c = tid + i * 256;
        if (A_KC) {
            int row = c / (BK / AVF), kc = c % (BK / AVF);
            aRow[i] = row; aKc[i] = kc * AVF;
            aMok[i] = (m0 + row) < M;
            aP[i] = Az + (long)(m0 + row) * ldA + kc * AVF;
        } else {
            int k = c / BM, m = c % BM;
            aRow[i] = m; aKc[i] = k;
            aMok[i] = (m0 + m) < M;
            aP[i] = Az + (long)k * ldA + (m0 + m);
        }
    }
    constexpr int BVF = BV / 4;
    constexpr int BCH = BN * BK / BVF;
    constexpr int BIT = BCH / 256;
    static_assert(BCH % 256 == 0, "B chunks divisible");
    const float* bP[BIT]; int bRow[BIT], bKc[BIT]; bool bNok[BIT];
    #pragma unroll
    for (int i = 0; i < BIT; i++) {
        int c = tid + i * 256;
        if (B_KC) {
            int row = c / (BK / BVF), kc = c % (BK / BVF);
            bRow[i] = row; bKc[i] = kc * BVF;
            bNok[i] = (n0 + row) < N;
            bP[i] = Bz + (long)(n0 + row) * ldB + kc * BVF;
        } else {
            int k = c / (BN / BVF), nc = c % (BN / BVF);
            bRow[i] = k; bKc[i] = nc * BVF;
            bNok[i] = (n0 + nc * BVF) < N;
            bP[i] = Bz + (long)k * ldB + n0 + nc * BVF;
        }
    }

    auto loadA = [&](int s, int k0) {
        float* dst = As0 + s * ASZ;
        #pragma unroll
        for (int i = 0; i < AIT; i++) {
            bool p = aMok[i] && (k0 + aKc[i]) < K;
            uint32_t d = sptr(dst + aRow[i] * LDAS + aKc[i]);
            if (A_KC) {
                if (AV == 16) cpa16(d, aP[i], p);
                else if (AV == 8) cpa8(d, aP[i], p);
                else cpa4(d, aP[i], p);
                aP[i] += BK;
            } else {
                cpa4(d, aP[i], p);
                aP[i] += (long)BK * ldA;
            }
        }
    };
    auto loadB = [&](int s, int k0) {
        float* dst = Bs0 + s * BSZ;
        #pragma unroll
        for (int i = 0; i < BIT; i++) {
            if (B_KC) {
                bool p = bNok[i] && (k0 + bKc[i]) < K;
                uint32_t d = sptr(dst + bRow[i] * LDBS + bKc[i]);
                if (BV == 16) cpa16(d, bP[i], p);
                else if (BV == 8) cpa8(d, bP[i], p);
                else cpa4(d, bP[i], p);
                bP[i] += BK;
            } else {
                bool p = bNok[i] && (k0 + bRow[i]) < K;
                uint32_t d = sptr(dst + bRow[i] * LDBS + bKc[i]);
                if (BV == 16) cpa16(d, bP[i], p);
                else if (BV == 8) cpa8(d, bP[i], p);
                else cpa4(d, bP[i], p);
                bP[i] += (long)BK * ldB;
            }
        }
    };

    wmma::fragment<wmma::accumulator, 16, 16, 8, float> acc[MI][NI];
    #pragma unroll
    for (int i = 0; i < MI; i++)
        #pragma unroll
        for (int j = 0; j < NI; j++)
            wmma::fill_fragment(acc[i][j], 0.0f);

    auto compute = [&](int s) {
        const float* as = As0 + s * ASZ;
        const float* bs = Bs0 + s * BSZ;
        #pragma unroll
        for (int kk = 0; kk < BK; kk += 8) {
            wmma::fragment<wmma::matrix_a, 16, 16, 8, wmma::precision::tf32, wmma::row_major> af[MI];
            #pragma unroll
            for (int i = 0; i < MI; i++) {
                wmma::load_matrix_sync(af[i], as + (warpM * WM + i * 16) * LDAS + kk, LDAS);
                #pragma unroll
                for (int t = 0; t < af[i].num_elements; t++)
                    af[i].x[t] = wmma::__float_to_tf32(af[i].x[t]);
            }
            if (B_KC) {
                wmma::fragment<wmma::matrix_b, 16, 16, 8, wmma::precision::tf32, wmma::col_major> bf[NI];
                #pragma unroll
                for (int j = 0; j < NI; j++) {
                    wmma::load_matrix_sync(bf[j], bs + (warpN * WN + j * 16) * LDBS + kk, LDBS);
                    #pragma unroll
                    for (int t = 0; t < bf[j].num_elements; t++)
                        bf[j].x[t] = wmma::__float_to_tf32(bf[j].x[t]);
                }
                #pragma unroll
                for (int i = 0; i < MI; i++)
                    #pragma unroll
                    for (int j = 0; j < NI; j++)
                        wmma::mma_sync(acc[i][j], af[i], bf[j], acc[i][j]);
            } else {
                wmma::fragment<wmma::matrix_b, 16, 16, 8, wmma::precision::tf32, wmma::row_major> bf[NI];
                #pragma unroll
                for (int j = 0; j < NI; j++) {
                    wmma::load_matrix_sync(bf[j], bs + kk * LDBS + warpN * WN + j * 16, LDBS);
                    #pragma unroll
                    for (int t = 0; t < bf[j].num_elements; t++)
                        bf[j].x[t] = wmma::__float_to_tf32(bf[j].x[t]);
                }
                #pragma unroll
                for (int i = 0; i < MI; i++)
                    #pragma unroll
                    for (int j = 0; j < NI; j++)
                        wmma::mma_sync(acc[i][j], af[i], bf[j], acc[i][j]);
            }
        }
    };

    const int T = (K + BK - 1) / BK;
    loadA(0, 0); loadB(0, 0); cp_commit();
    for (int t = 0; t < T; t++) {
        if (t + 1 < T) { loadA((t + 1) & 1, (t + 1) * BK); loadB((t + 1) & 1, (t + 1) * BK); }
        cp_commit();
        cp_wait<1>();
        __syncthreads();
        compute(t & 1);
        __syncthreads();
    }

    // ---- epilogue (smem free to reuse after last __syncthreads) ----
    float* ws = sm + wid * 256;
    const float gval = GAMMA ? gamma[0] : 0.0f;
    #pragma unroll
    for (int i = 0; i < MI; i++) {
        #pragma unroll
        for (int j = 0; j < NI; j++) {
            wmma::store_matrix_sync(ws, acc[i][j], 16, wmma::mem_row_major);
            __syncwarp();
            int gm0 = m0 + warpM * WM + i * 16;
            int gn0 = n0 + warpN * WN + j * 16;
            #pragma unroll
            for (int e0 = 0; e0 < 256; e0 += 32) {
                int e = e0 + lane;
                int r = e >> 4, c = e & 15;
                int gm = gm0 + r, gn = gn0 + c;
                if (gm < M && gn < N) {
                    float v = ws[e];
                    if (BIAS == 1) v += bias[gn];
                    else if (BIAS == 2) v += bias[gm];
                    if (GAMMA) v = gval * v + resid[(long)z * sRz + (long)gm * ldC + gn];
                    Cz[(long)gm * ldC + gn] = v;
                }
            }
            __syncwarp();
        }
    }
}

// ---------------------------------------------------------------------------
// Row softmax over length-150 rows; one warp per row.
// ---------------------------------------------------------------------------
__global__ __launch_bounds__(256)
void softmax150(float* __restrict__ att, int rows)
{
    int row  = blockIdx.x * 8 + (threadIdx.x >> 5);
    int lane = threadIdx.x & 31;
    if (row >= rows) return;
    float* p = att + (long)row * LL;

    float v[5];
    float mx = -1e30f;
    #pragma unroll
    for (int i = 0; i < 5; i++) {
        int j = lane + 32 * i;
        v[i] = (j < LL) ? p[j] : -1e30f;
        mx = fmaxf(mx, v[i]);
    }
    #pragma unroll
    for (int o = 16; o > 0; o >>= 1) mx = fmaxf(mx, __shfl_xor_sync(0xffffffffu, mx, o));

    float s = 0.0f;
    #pragma unroll
    for (int i = 0; i < 5; i++) { v[i] = expf(v[i] - mx); s += v[i]; }
    #pragma unroll
    for (int o = 16; o > 0; o >>= 1) s += __shfl_xor_sync(0xffffffffu, s, o);

    float inv = 1.0f / s;
    #pragma unroll
    for (int i = 0; i < 5; i++) {
        int j = lane + 32 * i;
        if (j < LL) p[j] = v[i] * inv;
    }
}

// ---------------------------------------------------------------------------
extern "C" void kernel_launch(void* const* d_in, const int* in_sizes, int n_in,
                              void* d_out, int out_size)
{
    (void)in_sizes; (void)n_in; (void)out_size;
    const float* x     = (const float*)d_in[0];
    const float* Wv    = (const float*)d_in[1];
    const float* bv    = (const float*)d_in[2];
    const float* Wq    = (const float*)d_in[3];
    const float* bq    = (const float*)d_in[4];
    const float* Wk    = (const float*)d_in[5];
    const float* bk    = (const float*)d_in[6];
    const float* gamma = (const float*)d_in[7];
    const float* W1    = (const float*)d_in[8];
    const float* b1    = (const float*)d_in[9];
    const float* W2    = (const float*)d_in[10];
    const float* b2    = (const float*)d_in[11];
    float* out = (float*)d_out;

    float *pv, *q, *k, *att, *o2, *h;
    cudaGetSymbolAddress((void**)&pv,  g_pv);
    cudaGetSymbolAddress((void**)&q,   g_q);
    cudaGetSymbolAddress((void**)&k,   g_k);
    cudaGetSymbolAddress((void**)&att, g_att);
    cudaGetSymbolAddress((void**)&o2,  g_o2);
    cudaGetSymbolAddress((void**)&h,   g_h);

    const long CL   = (long)CC * LL;     // 38400
    const long XL   = (long)CIN * LL;    // 307200
    const long LLsq = (long)LL * LL;     // 22500

    // kernel pointers
    auto kPV  = &gemm2<128, 64, 32, 32, 32, true, 16, false, 8, 2, false>; // pv, q, k
    auto kEN  = &gemm2<128, 64, 32, 32, 32, false, 4, false, 8, 0, false>; // energy
    auto kAO  = &gemm2<128, 64, 32, 32, 32, true,  8, true,  8, 0, true >; // attn-out
    auto kFC1 = &gemm2<128, 128, 32, 64, 32, true, 16, true, 16, 1, false>;
    auto kFC2 = &gemm2<64,  128, 32, 32, 32, true, 16, true, 16, 1, false>;

    // dynamic smem sizes (floats): 2*(BM*(BK+4) + (B_KC? BN*(BK+4) : BK*(BN+4)))
    const size_t smPV  = 2 * (128 * 36 + 32 * 68) * sizeof(float);  // 54272
    const size_t smEN  = smPV;
    const size_t smAO  = 2 * (128 * 36 + 64 * 36) * sizeof(float);  // 55296
    const size_t smFC1 = 2 * (128 * 36 + 128 * 36) * sizeof(float); // 73728
    const size_t smFC2 = 2 * (64 * 36 + 128 * 36) * sizeof(float);  // 55296

    cudaFuncSetAttribute(kPV,  cudaFuncAttributeMaxDynamicSharedMemorySize, (int)smPV);
    cudaFuncSetAttribute(kEN,  cudaFuncAttributeMaxDynamicSharedMemorySize, (int)smEN);
    cudaFuncSetAttribute(kAO,  cudaFuncAttributeMaxDynamicSharedMemorySize, (int)smAO);
    cudaFuncSetAttribute(kFC1, cudaFuncAttributeMaxDynamicSharedMemorySize, (int)smFC1);
    cudaFuncSetAttribute(kFC2, cudaFuncAttributeMaxDynamicSharedMemorySize, (int)smFC2);

    dim3 blk(256);

    // pv[b,o,l] = Wv[o,c] x[b,c,l] + bv[o]          M=256 N=150 K=2048
    kPV<<<dim3(3, 2, NB), blk, smPV>>>(
        Wv, CIN, 0,  x, LL, XL,  pv, LL, CL,  bv, nullptr, 0, nullptr,
        CC, LL, CIN);

    // q = Wq pv + bq ; k = Wk pv + bk               M=256 N=150 K=256
    kPV<<<dim3(3, 2, NB), blk, smPV>>>(
        Wq, CC, 0,  pv, LL, CL,  q, LL, CL,  bq, nullptr, 0, nullptr,
        CC, LL, CC);
    kPV<<<dim3(3, 2, NB), blk, smPV>>>(
        Wk, CC, 0,  pv, LL, CL,  k, LL, CL,  bk, nullptr, 0, nullptr,
        CC, LL, CC);

    // energy[b,i,j] = sum_c q[b,c,i] k[b,c,j]       M=150 N=150 K=256
    kEN<<<dim3(3, 2, NB), blk, smEN>>>(
        q, LL, CL,  k, LL, CL,  att, LL, LLsq,  nullptr, nullptr, 0, nullptr,
        LL, LL, CC);

    // softmax over last axis, in place
    softmax150<<<(NB * LL + 7) / 8, blk>>>(att, NB * LL);

    // out2[b,c,l] = gamma * sum_m pv[b,c,m] att[b,l,m] + pv[b,c,l]
    //                                               M=256 N=150 K=150
    kAO<<<dim3(3, 2, NB), blk, smAO>>>(
        pv, LL, CL,  att, LL, LLsq,  o2, LL, CL,  nullptr, pv, CL, gamma,
        CC, LL, LL);

    // fc1: h[b,j] = flat[b,:] . W1[j,:] + b1[j]     M=256 N=8192 K=38400
    kFC1<<<dim3(H1 / 128, 2, 1), blk, smFC1>>>(
        o2, CL, 0,  W1, CL, 0,  h, H1, 0,  b1, nullptr, 0, nullptr,
        NB, H1, (int)CL);

    // fc2: out[b,j] = h[b,:] . W2[j,:] + b2[j]      M=256 N=2048 K=8192
    kFC2<<<dim3(NOUT / 128, 4, 1), blk, smFC2>>>(
        h, H1, 0,  W2, H1, 0,  out, NOUT, 0,  b2, nullptr, 0, nullptr,
        NB, NOUT, H1);
}